// round 7
// baseline (speedup 1.0000x reference)
#include <cuda_runtime.h>
#include <cuda_bf16.h>
#include <cstdint>

// ---------------- problem constants ----------------
#define N_USERS   50000
#define N_ITEMS   10000
#define N_NODES   100000
#define EMB       64
#define NNZ       1600000
#define VIS_DIM   2048
#define TXT_DIM   300
#define OUT_COLS  192   // emb * 3

// ---------------- device scratch (static, allocation-free) ----------------
__device__ float g_H1v[N_ITEMS * 512];    // relu(visual @ Wv1^T + bv1)
__device__ float g_H1t[N_ITEMS * 256];    // relu(text  @ Wt1^T + bt1)
__device__ float g_nb [N_NODES * EMB];    // SpMM accumulator
__device__ float g_Wv2d[64 * 512];        // Wd @ Wv2
__device__ float g_Wt2d[64 * 256];        // Wd @ Wt2
__device__ float g_bfuse[64];             // Wd@(bv2+bt2) + 2*bd

// ---------------- weight combination (tiny) ----------------
__global__ void combine_w(const float* __restrict__ Wd, const float* __restrict__ bd,
                          const float* __restrict__ Wv2, const float* __restrict__ bv2,
                          const float* __restrict__ Wt2, const float* __restrict__ bt2)
{
    int idx = blockIdx.x * blockDim.x + threadIdx.x;
    if (idx < 64 * 512) {
        int d = idx >> 9, k = idx & 511;
        float s = 0.f;
        #pragma unroll 8
        for (int o = 0; o < 64; o++) s += Wd[d * 64 + o] * Wv2[o * 512 + k];
        g_Wv2d[idx] = s;
    } else if (idx < 64 * 512 + 64 * 256) {
        int j = idx - 64 * 512;
        int d = j >> 8, k = j & 255;
        float s = 0.f;
        #pragma unroll 8
        for (int o = 0; o < 64; o++) s += Wd[d * 64 + o] * Wt2[o * 256 + k];
        g_Wt2d[j] = s;
    } else if (idx < 64 * 512 + 64 * 256 + 64) {
        int d = idx - (64 * 512 + 64 * 256);
        float s = 2.f * bd[d];
        #pragma unroll 8
        for (int o = 0; o < 64; o++) s += Wd[d * 64 + o] * (bv2[o] + bt2[o]);
        g_bfuse[d] = s;
    }
}

// ---------------- ego copy: embedding -> out[:, 0:64] ----------------
__global__ void copy_ego(const float* __restrict__ emb, float* __restrict__ out)
{
    int i = blockIdx.x * blockDim.x + threadIdx.x;   // over N_NODES*16 float4s
    if (i >= N_NODES * 16) return;
    int row = i >> 4, c = i & 15;
    *(float4*)(out + (size_t)row * OUT_COLS + c * 4) =
        *(const float4*)(emb + (size_t)row * EMB + c * 4);
}

// ---------------- zero SpMM accumulator ----------------
__global__ void zero_nb()
{
    int i = blockIdx.x * blockDim.x + threadIdx.x;
    if (i < N_NODES * 16) ((float4*)g_nb)[i] = make_float4(0.f, 0.f, 0.f, 0.f);
}

// ---------------- big SGEMM: C = relu(A @ B^T + bias) --------------------
// A [M,K] row-major, B [N,K] row-major (both K contiguous). BM=BN=128, BK=16,
// 256 threads, 8x8 per thread, double-buffered smem, one sync per K-tile.
// N must be a multiple of 128.
template <bool VEC4>
__global__ __launch_bounds__(256, 2)
void sgemm_nt_relu(const float* __restrict__ A, const float* __restrict__ B,
                   const float* __restrict__ bias, float* __restrict__ C,
                   int M, int N, int K)
{
    const int BM = 128, BN = 128, BK = 16;
    __shared__ float As[2][BK][BM];
    __shared__ float Bs[2][BK][BN];

    int tid = threadIdx.x;
    int ty = tid >> 4;        // 0..15 -> row group
    int tx = tid & 15;        // 0..15 -> col group
    int lrow  = tid >> 1;     // 0..127
    int lkoff = (tid & 1) * 8;   // 0 or 8: this thread's 8 consecutive k's

    int aRow = blockIdx.y * BM + lrow;
    int aRowC = aRow < M ? aRow : M - 1;
    int bRow = blockIdx.x * BN + lrow;   // N % 128 == 0 guaranteed

    const float* Arow = A + (size_t)aRowC * K;
    const float* Brow = B + (size_t)bRow  * K;

    float acc[8][8];
    #pragma unroll
    for (int i = 0; i < 8; i++)
        #pragma unroll
        for (int j = 0; j < 8; j++) acc[i][j] = 0.f;

    // prefetch registers (tile staged from GMEM before STS)
    float a_ld[8], b_ld[8];

    auto ldg = [&](int k0) {
        if (VEC4) {
            float4 a0 = *(const float4*)(Arow + k0 + lkoff);
            float4 a1 = *(const float4*)(Arow + k0 + lkoff + 4);
            a_ld[0] = a0.x; a_ld[1] = a0.y; a_ld[2] = a0.z; a_ld[3] = a0.w;
            a_ld[4] = a1.x; a_ld[5] = a1.y; a_ld[6] = a1.z; a_ld[7] = a1.w;
            float4 b0 = *(const float4*)(Brow + k0 + lkoff);
            float4 b1 = *(const float4*)(Brow + k0 + lkoff + 4);
            b_ld[0] = b0.x; b_ld[1] = b0.y; b_ld[2] = b0.z; b_ld[3] = b0.w;
            b_ld[4] = b1.x; b_ld[5] = b1.y; b_ld[6] = b1.z; b_ld[7] = b1.w;
        } else {
            #pragma unroll
            for (int j = 0; j < 8; j++) {
                int k = k0 + lkoff + j;
                a_ld[j] = (k < K) ? Arow[k] : 0.f;
                b_ld[j] = (k < K) ? Brow[k] : 0.f;
            }
        }
    };
    auto sts = [&](int buf) {
        #pragma unroll
        for (int j = 0; j < 8; j++) {
            As[buf][lkoff + j][lrow] = a_ld[j];
            Bs[buf][lkoff + j][lrow] = b_ld[j];
        }
    };

    int T = (K + BK - 1) / BK;    // number of K-tiles
    ldg(0);
    sts(0);
    __syncthreads();

    for (int t = 0; t < T; t++) {
        if (t + 1 < T) ldg((t + 1) * BK);   // prefetch next tile into regs

        int cur = t & 1;
        #pragma unroll
        for (int k = 0; k < BK; k++) {
            float4 a0 = *(const float4*)&As[cur][k][ty * 8];
            float4 a1 = *(const float4*)&As[cur][k][ty * 8 + 4];
            float4 b0 = *(const float4*)&Bs[cur][k][tx * 8];
            float4 b1 = *(const float4*)&Bs[cur][k][tx * 8 + 4];
            float a[8] = {a0.x, a0.y, a0.z, a0.w, a1.x, a1.y, a1.z, a1.w};
            float b[8] = {b0.x, b0.y, b0.z, b0.w, b1.x, b1.y, b1.z, b1.w};
            #pragma unroll
            for (int i = 0; i < 8; i++)
                #pragma unroll
                for (int j = 0; j < 8; j++) acc[i][j] += a[i] * b[j];
        }

        if (t + 1 < T) sts((t + 1) & 1);    // write other buffer (disjoint from reads)
        __syncthreads();                     // guards next iter's reads + 2-ago reuse
    }

    int n0 = blockIdx.x * BN + tx * 8;
    float bs[8];
    #pragma unroll
    for (int j = 0; j < 8; j++) bs[j] = bias[n0 + j];

    #pragma unroll
    for (int i = 0; i < 8; i++) {
        int m = blockIdx.y * BM + ty * 8 + i;
        if (m < M) {
            float v[8];
            #pragma unroll
            for (int j = 0; j < 8; j++) v[j] = fmaxf(acc[i][j] + bs[j], 0.f);
            *(float4*)(C + (size_t)m * N + n0)     = make_float4(v[0], v[1], v[2], v[3]);
            *(float4*)(C + (size_t)m * N + n0 + 4) = make_float4(v[4], v[5], v[6], v[7]);
        }
    }
}

// ---------------- small GEMM with N=64, split-K two-part inputs ----------
// C[m,n] = epi( sum_{k<K1} A1[m,k]B1[n,k] + sum_{k<K2} A2[m,k]B2[n,k] + bias[n] )
// mode 0: 0.5*(acc+bias)  (fusion epilogue)
// mode 1: leaky_relu(acc+bias, 0.01)
// Requires K1 % 16 == 0, K2 % 16 == 0, all ld* multiples of 4, 16B-aligned ptrs.
// Double-buffered smem, one sync per K-tile.
__global__ __launch_bounds__(256, 2)
void gemm_n64(const float* __restrict__ A1, int lda1, int K1,
              const float* __restrict__ A2, int lda2, int K2,
              const float* __restrict__ B1, int ldb1,
              const float* __restrict__ B2, int ldb2,
              const float* __restrict__ bias,
              float* __restrict__ C, int ldc, int M, int mode)
{
    const int BM = 128, BK = 16;
    __shared__ float As[2][BK][BM];
    __shared__ float Bs[2][BK][64];

    int tid = threadIdx.x;
    int rg = tid & 31;         // lane -> row sub
    int cg = tid >> 5;         // warp -> col group (8 cols)

    int lrowA = tid >> 1;                 // 0..127
    int lkA   = (tid & 1) * 8;            // 0 or 8
    int rA = blockIdx.x * BM + lrowA;
    int rAc = rA < M ? rA : M - 1;

    int lnB = tid >> 2;                   // 0..63
    int lkB = (tid & 3) * 4;              // 0,4,8,12

    float acc[4][8];
    #pragma unroll
    for (int i = 0; i < 4; i++)
        #pragma unroll
        for (int j = 0; j < 8; j++) acc[i][j] = 0.f;

    // prefetch registers
    float a_ld[8], b_ld[4];

    auto ldg = [&](int k0) {   // k0 = K-offset of tile start; tiles never straddle K1
        const float* Ap; const float* Bp; int lda, ldb, kb;
        if (k0 < K1) { Ap = A1; Bp = B1; lda = lda1; ldb = ldb1; kb = k0; }
        else         { Ap = A2; Bp = B2; lda = lda2; ldb = ldb2; kb = k0 - K1; }
        float4 v0 = *(const float4*)(Ap + (size_t)rAc * lda + kb + lkA);
        float4 v1 = *(const float4*)(Ap + (size_t)rAc * lda + kb + lkA + 4);
        a_ld[0] = v0.x; a_ld[1] = v0.y; a_ld[2] = v0.z; a_ld[3] = v0.w;
        a_ld[4] = v1.x; a_ld[5] = v1.y; a_ld[6] = v1.z; a_ld[7] = v1.w;
        float4 w = *(const float4*)(Bp + (size_t)lnB * ldb + kb + lkB);
        b_ld[0] = w.x; b_ld[1] = w.y; b_ld[2] = w.z; b_ld[3] = w.w;
    };
    auto sts = [&](int buf) {
        #pragma unroll
        for (int j = 0; j < 8; j++) As[buf][lkA + j][lrowA] = a_ld[j];
        #pragma unroll
        for (int j = 0; j < 4; j++) Bs[buf][lkB + j][lnB] = b_ld[j];
    };

    int K = K1 + K2;
    int T = K / BK;            // K1, K2 both multiples of BK
    ldg(0);
    sts(0);
    __syncthreads();

    for (int t = 0; t < T; t++) {
        if (t + 1 < T) ldg((t + 1) * BK);

        int cur = t & 1;
        #pragma unroll
        for (int k = 0; k < BK; k++) {
            float a0 = As[cur][k][rg];
            float a1 = As[cur][k][rg + 32];
            float a2 = As[cur][k][rg + 64];
            float a3 = As[cur][k][rg + 96];
            float4 b0 = *(const float4*)&Bs[cur][k][cg * 8];
            float4 b1 = *(const float4*)&Bs[cur][k][cg * 8 + 4];
            float b[8] = {b0.x, b0.y, b0.z, b0.w, b1.x, b1.y, b1.z, b1.w};
            #pragma unroll
            for (int j = 0; j < 8; j++) {
                acc[0][j] += a0 * b[j];
                acc[1][j] += a1 * b[j];
                acc[2][j] += a2 * b[j];
                acc[3][j] += a3 * b[j];
            }
        }

        if (t + 1 < T) sts((t + 1) & 1);
        __syncthreads();
    }

    float bs[8];
    #pragma unroll
    for (int j = 0; j < 8; j++) bs[j] = bias[cg * 8 + j];

    #pragma unroll
    for (int i = 0; i < 4; i++) {
        int m = blockIdx.x * BM + rg + 32 * i;
        if (m < M) {
            float v[8];
            #pragma unroll
            for (int j = 0; j < 8; j++) {
                float t = acc[i][j] + bs[j];
                v[j] = (mode == 0) ? 0.5f * t : (t > 0.f ? t : 0.01f * t);
            }
            *(float4*)(C + (size_t)m * ldc + cg * 8)     = make_float4(v[0], v[1], v[2], v[3]);
            *(float4*)(C + (size_t)m * ldc + cg * 8 + 4) = make_float4(v[4], v[5], v[6], v[7]);
        }
    }
}

// ---------------- SpMM scatter: nb[row] += val * cur[col] ----------------
// 16 lanes per edge, each lane handles one float4 of the 64-wide row.
__global__ __launch_bounds__(256)
void spmm_scatter(const int* __restrict__ rows, const int* __restrict__ cols,
                  const float* __restrict__ vals,
                  const float* __restrict__ cur, int ld_cur)
{
    long t = (long)blockIdx.x * blockDim.x + threadIdx.x;
    int e = (int)(t >> 4);
    int c = (int)(t & 15);
    if (e >= NNZ) return;
    int r = rows[e];
    int cl = cols[e];
    float v = vals[e];
    float4 x = *(const float4*)(cur + (size_t)cl * ld_cur + c * 4);
    float* dst = g_nb + (size_t)r * EMB + c * 4;
    asm volatile("red.global.add.v4.f32 [%0], {%1, %2, %3, %4};"
                 :: "l"(dst), "f"(x.x * v), "f"(x.y * v), "f"(x.z * v), "f"(x.w * v)
                 : "memory");
}

// ---------------- launch ----------------
extern "C" void kernel_launch(void* const* d_in, const int* in_sizes, int n_in,
                              void* d_out, int out_size)
{
    const int*   adj_row = (const int*)  d_in[0];
    const int*   adj_col = (const int*)  d_in[1];
    const float* adj_val = (const float*)d_in[2];
    const float* embedding = (const float*)d_in[3];
    const float* visual  = (const float*)d_in[4];
    const float* text    = (const float*)d_in[5];
    const float* Wv1 = (const float*)d_in[6];  const float* bv1 = (const float*)d_in[7];
    const float* Wv2 = (const float*)d_in[8];  const float* bv2 = (const float*)d_in[9];
    const float* Wt1 = (const float*)d_in[10]; const float* bt1 = (const float*)d_in[11];
    const float* Wt2 = (const float*)d_in[12]; const float* bt2 = (const float*)d_in[13];
    const float* Wd  = (const float*)d_in[14]; const float* bd  = (const float*)d_in[15];
    const float* Wc0 = (const float*)d_in[16]; const float* bc0 = (const float*)d_in[17];
    const float* Wc1 = (const float*)d_in[18]; const float* bc1 = (const float*)d_in[19];
    float* out = (float*)d_out;

    float *pH1v, *pH1t, *pNb, *pWv2d, *pWt2d, *pBfuse;
    cudaGetSymbolAddress((void**)&pH1v,  g_H1v);
    cudaGetSymbolAddress((void**)&pH1t,  g_H1t);
    cudaGetSymbolAddress((void**)&pNb,   g_nb);
    cudaGetSymbolAddress((void**)&pWv2d, g_Wv2d);
    cudaGetSymbolAddress((void**)&pWt2d, g_Wt2d);
    cudaGetSymbolAddress((void**)&pBfuse,g_bfuse);

    // 1. fold Wd into the second-layer weights/biases
    combine_w<<<(64*512 + 64*256 + 64 + 255) / 256, 256>>>(Wd, bd, Wv2, bv2, Wt2, bt2);

    // 2. ego = embedding (item rows overwritten by fusion below)
    copy_ego<<<(N_NODES * 16 + 255) / 256, 256>>>(embedding, out);

    // 3. H1v = relu(visual @ Wv1^T + bv1)   [10000, 512], K=2048
    {
        dim3 grid(512 / 128, (N_ITEMS + 127) / 128);
        sgemm_nt_relu<true><<<grid, 256>>>(visual, Wv1, bv1, pH1v, N_ITEMS, 512, VIS_DIM);
    }
    // 4. H1t = relu(text @ Wt1^T + bt1)     [10000, 256], K=300
    {
        dim3 grid(256 / 128, (N_ITEMS + 127) / 128);
        sgemm_nt_relu<false><<<grid, 256>>>(text, Wt1, bt1, pH1t, N_ITEMS, 256, TXT_DIM);
    }
    // 5. fused_item -> ego item rows: 0.5*(H1v@Wv2d^T + H1t@Wt2d^T + bfuse)
    gemm_n64<<<(N_ITEMS + 127) / 128, 256>>>(
        pH1v, 512, 512, pH1t, 256, 256,
        pWv2d, 512, pWt2d, 256,
        pBfuse, out + (size_t)N_USERS * OUT_COLS, OUT_COLS, N_ITEMS, 0);

    // ---- layer 1 ----
    zero_nb<<<(N_NODES * 16 + 255) / 256, 256>>>();
    spmm_scatter<<<(int)(((long)NNZ * 16 + 255) / 256), 256>>>(
        adj_row, adj_col, adj_val, out /*ego, cols 0:64*/, OUT_COLS);
    gemm_n64<<<(N_NODES + 127) / 128, 256>>>(
        out, OUT_COLS, 64, pNb, EMB, 64,
        Wc0, 128, Wc0 + 64, 128,
        bc0, out + 64, OUT_COLS, N_NODES, 1);

    // ---- layer 2 ----
    zero_nb<<<(N_NODES * 16 + 255) / 256, 256>>>();
    spmm_scatter<<<(int)(((long)NNZ * 16 + 255) / 256), 256>>>(
        adj_row, adj_col, adj_val, out + 64 /*cur1, cols 64:128*/, OUT_COLS);
    gemm_n64<<<(N_NODES + 127) / 128, 256>>>(
        out + 64, OUT_COLS, 64, pNb, EMB, 64,
        Wc1, 128, Wc1 + 64, 128,
        bc1, out + 128, OUT_COLS, N_NODES, 1);
}

// round 8
// speedup vs baseline: 1.6863x; 1.6863x over previous
#include <cuda_runtime.h>
#include <cuda_bf16.h>
#include <cstdint>

// ---------------- problem constants ----------------
#define N_USERS   50000
#define N_ITEMS   10000
#define N_NODES   100000
#define EMB       64
#define NNZ       1600000
#define VIS_DIM   2048
#define TXT_DIM   300
#define OUT_COLS  192   // emb * 3

// ---------------- device scratch (static, allocation-free) ----------------
__device__ float g_H1v[N_ITEMS * 512];    // relu(visual @ Wv1^T + bv1)
__device__ float g_H1t[N_ITEMS * 256];    // relu(text  @ Wt1^T + bt1)
__device__ float g_nb [N_NODES * EMB];    // SpMM accumulator
__device__ float g_Wv2d[64 * 512];        // Wd @ Wv2
__device__ float g_Wt2d[64 * 256];        // Wd @ Wt2
__device__ float g_bfuse[64];             // Wd@(bv2+bt2) + 2*bd

// ---------------- weight combination (tiny) ----------------
__global__ void combine_w(const float* __restrict__ Wd, const float* __restrict__ bd,
                          const float* __restrict__ Wv2, const float* __restrict__ bv2,
                          const float* __restrict__ Wt2, const float* __restrict__ bt2)
{
    int idx = blockIdx.x * blockDim.x + threadIdx.x;
    if (idx < 64 * 512) {
        int d = idx >> 9, k = idx & 511;
        float s = 0.f;
        #pragma unroll 8
        for (int o = 0; o < 64; o++) s += Wd[d * 64 + o] * Wv2[o * 512 + k];
        g_Wv2d[idx] = s;
    } else if (idx < 64 * 512 + 64 * 256) {
        int j = idx - 64 * 512;
        int d = j >> 8, k = j & 255;
        float s = 0.f;
        #pragma unroll 8
        for (int o = 0; o < 64; o++) s += Wd[d * 64 + o] * Wt2[o * 256 + k];
        g_Wt2d[j] = s;
    } else if (idx < 64 * 512 + 64 * 256 + 64) {
        int d = idx - (64 * 512 + 64 * 256);
        float s = 2.f * bd[d];
        #pragma unroll 8
        for (int o = 0; o < 64; o++) s += Wd[d * 64 + o] * (bv2[o] + bt2[o]);
        g_bfuse[d] = s;
    }
}

// ---------------- ego copy: embedding -> out[:, 0:64] ----------------
__global__ void copy_ego(const float* __restrict__ emb, float* __restrict__ out)
{
    int i = blockIdx.x * blockDim.x + threadIdx.x;   // over N_NODES*16 float4s
    if (i >= N_NODES * 16) return;
    int row = i >> 4, c = i & 15;
    *(float4*)(out + (size_t)row * OUT_COLS + c * 4) =
        *(const float4*)(emb + (size_t)row * EMB + c * 4);
}

// ---------------- zero SpMM accumulator ----------------
__global__ void zero_nb()
{
    int i = blockIdx.x * blockDim.x + threadIdx.x;
    if (i < N_NODES * 16) ((float4*)g_nb)[i] = make_float4(0.f, 0.f, 0.f, 0.f);
}

// ---------------- tf32 tensor-core GEMM: C = relu(A @ B^T + bias) --------
// A [M,K] row-major, B [N,K] row-major. BM=BN=128, BK=16, 256 threads,
// 8 warps each computing 64x32 via mma.m16n8k8.tf32. cp.async double buffer.
// N must be a multiple of 128. Non-VEC4 path zero-fills the K tail.
template <bool VEC4>
__global__ __launch_bounds__(256, 2)
void mma_nt_relu(const float* __restrict__ A, const float* __restrict__ B,
                 const float* __restrict__ bias, float* __restrict__ C,
                 int M, int N, int K)
{
    const int BK = 16, LDT = 20;   // +4 pad: ldmatrix rows land on disjoint bank quads
    __shared__ float As[2][128][LDT];
    __shared__ float Bs[2][128][LDT];

    int tid = threadIdx.x;
    int lane = tid & 31, wid = tid >> 5;
    int wm = wid >> 2;     // 0..1 : 64-row half
    int wn = wid & 3;      // 0..3 : 32-col quarter

    // ---- gmem->smem copy mapping (2 threads per row, 8 floats each) ----
    int row  = tid >> 1;          // 0..127
    int koff = (tid & 1) * 8;     // 0 or 8
    int aRow = blockIdx.y * 128 + row;
    int aRowC = aRow < M ? aRow : M - 1;
    int bRow = blockIdx.x * 128 + row;    // always < N (N % 128 == 0)
    const float* Arow = A + (size_t)aRowC * K + koff;
    const float* Brow = B + (size_t)bRow  * K + koff;

    uint32_t uA[2], uB[2];
    uA[0] = (uint32_t)__cvta_generic_to_shared(&As[0][row][koff]);
    uA[1] = (uint32_t)__cvta_generic_to_shared(&As[1][row][koff]);
    uB[0] = (uint32_t)__cvta_generic_to_shared(&Bs[0][row][koff]);
    uB[1] = (uint32_t)__cvta_generic_to_shared(&Bs[1][row][koff]);

    auto issue = [&](int k0, int buf) {
        #pragma unroll
        for (int c = 0; c < 2; c++) {
            int sz;
            if (VEC4) sz = 16;
            else {
                int rem = K - (k0 + koff + c * 4);      // floats still valid
                sz = rem >= 4 ? 16 : (rem > 0 ? rem * 4 : 0);
            }
            asm volatile("cp.async.ca.shared.global [%0], [%1], 16, %2;"
                         :: "r"(uA[buf] + c * 16), "l"(Arow + k0 + c * 4), "r"(sz) : "memory");
            asm volatile("cp.async.ca.shared.global [%0], [%1], 16, %2;"
                         :: "r"(uB[buf] + c * 16), "l"(Brow + k0 + c * 4), "r"(sz) : "memory");
        }
        asm volatile("cp.async.commit_group;" ::: "memory");
    };

    // ---- ldmatrix per-lane base addresses ----
    // A fragment (m16n8k8): x4 matrices = (rows 0-7, k 0-3),(rows 8-15, k 0-3),
    //                                     (rows 0-7, k 4-7),(rows 8-15, k 4-7)
    int l = lane & 7;
    int selA = lane >> 3;                       // which of the 4 matrices this lane addresses
    int arow0 = wm * 64 + (selA & 1) * 8 + l;
    int acol0 = (selA >> 1) * 4;
    uint32_t aBase[2];
    aBase[0] = (uint32_t)__cvta_generic_to_shared(&As[0][arow0][acol0]);
    aBase[1] = (uint32_t)__cvta_generic_to_shared(&As[1][arow0][acol0]);
    // B fragment: x2 matrices = (n 0-7, k 0-3),(n 0-7, k 4-7)
    int l16 = lane & 15;
    int brow0 = wn * 32 + (l16 & 7);
    int bcol0 = (l16 >> 3) * 4;
    uint32_t bBase[2];
    bBase[0] = (uint32_t)__cvta_generic_to_shared(&Bs[0][brow0][bcol0]);
    bBase[1] = (uint32_t)__cvta_generic_to_shared(&Bs[1][brow0][bcol0]);

    float acc[4][4][4];
    #pragma unroll
    for (int i = 0; i < 4; i++)
        #pragma unroll
        for (int j = 0; j < 4; j++)
            #pragma unroll
            for (int r = 0; r < 4; r++) acc[i][j][r] = 0.f;

    int T = (K + BK - 1) / BK;
    issue(0, 0);
    asm volatile("cp.async.wait_group 0;" ::: "memory");
    __syncthreads();

    for (int t = 0; t < T; t++) {
        if (t + 1 < T) issue((t + 1) * BK, (t + 1) & 1);

        int cur = t & 1;
        #pragma unroll
        for (int ks = 0; ks < 2; ks++) {
            uint32_t af[4][4], bf[4][2];
            #pragma unroll
            for (int i = 0; i < 4; i++) {
                uint32_t addr = aBase[cur] + (uint32_t)((i * 16 * LDT + ks * 8) * 4);
                asm volatile("ldmatrix.sync.aligned.m8n8.x4.shared.b16 {%0,%1,%2,%3}, [%4];"
                    : "=r"(af[i][0]), "=r"(af[i][1]), "=r"(af[i][2]), "=r"(af[i][3])
                    : "r"(addr));
            }
            #pragma unroll
            for (int j = 0; j < 4; j++) {
                uint32_t addr = bBase[cur] + (uint32_t)((j * 8 * LDT + ks * 8) * 4);
                asm volatile("ldmatrix.sync.aligned.m8n8.x2.shared.b16 {%0,%1}, [%2];"
                    : "=r"(bf[j][0]), "=r"(bf[j][1])
                    : "r"(addr));
            }
            // round fp32 -> tf32 (rna: unbiased, ~2^-12 rms)
            #pragma unroll
            for (int i = 0; i < 4; i++)
                #pragma unroll
                for (int r = 0; r < 4; r++)
                    asm("cvt.rna.tf32.f32 %0, %0;" : "+r"(af[i][r]));
            #pragma unroll
            for (int j = 0; j < 4; j++)
                #pragma unroll
                for (int r = 0; r < 2; r++)
                    asm("cvt.rna.tf32.f32 %0, %0;" : "+r"(bf[j][r]));

            #pragma unroll
            for (int i = 0; i < 4; i++)
                #pragma unroll
                for (int j = 0; j < 4; j++)
                    asm volatile(
                        "mma.sync.aligned.m16n8k8.row.col.f32.tf32.tf32.f32 "
                        "{%0,%1,%2,%3}, {%4,%5,%6,%7}, {%8,%9}, {%0,%1,%2,%3};"
                        : "+f"(acc[i][j][0]), "+f"(acc[i][j][1]),
                          "+f"(acc[i][j][2]), "+f"(acc[i][j][3])
                        : "r"(af[i][0]), "r"(af[i][1]), "r"(af[i][2]), "r"(af[i][3]),
                          "r"(bf[j][0]), "r"(bf[j][1]));
        }

        if (t + 1 < T) asm volatile("cp.async.wait_group 0;" ::: "memory");
        __syncthreads();
    }

    // ---- epilogue: bias + relu, float2 stores ----
    int g = lane >> 2, tq = lane & 3;
    #pragma unroll
    for (int i = 0; i < 4; i++) {
        int m0 = blockIdx.y * 128 + wm * 64 + i * 16 + g;
        #pragma unroll
        for (int j = 0; j < 4; j++) {
            int n0 = blockIdx.x * 128 + wn * 32 + j * 8 + 2 * tq;
            float bv0 = bias[n0], bv1 = bias[n0 + 1];
            if (m0 < M) {
                float2 v = make_float2(fmaxf(acc[i][j][0] + bv0, 0.f),
                                       fmaxf(acc[i][j][1] + bv1, 0.f));
                *(float2*)(C + (size_t)m0 * N + n0) = v;
            }
            if (m0 + 8 < M) {
                float2 v = make_float2(fmaxf(acc[i][j][2] + bv0, 0.f),
                                       fmaxf(acc[i][j][3] + bv1, 0.f));
                *(float2*)(C + (size_t)(m0 + 8) * N + n0) = v;
            }
        }
    }
}

// ---------------- small GEMM with N=64, split-K two-part inputs ----------
// C[m,n] = epi( sum_{k<K1} A1[m,k]B1[n,k] + sum_{k<K2} A2[m,k]B2[n,k] + bias[n] )
// mode 0: 0.5*(acc+bias)  (fusion epilogue)
// mode 1: leaky_relu(acc+bias, 0.01)
// Requires K1 % 16 == 0, K2 % 16 == 0, all ld* multiples of 4, 16B-aligned ptrs.
// Double-buffered smem, one sync per K-tile.
__global__ __launch_bounds__(256, 2)
void gemm_n64(const float* __restrict__ A1, int lda1, int K1,
              const float* __restrict__ A2, int lda2, int K2,
              const float* __restrict__ B1, int ldb1,
              const float* __restrict__ B2, int ldb2,
              const float* __restrict__ bias,
              float* __restrict__ C, int ldc, int M, int mode)
{
    const int BM = 128, BK = 16;
    __shared__ float As[2][BK][BM];
    __shared__ float Bs[2][BK][64];

    int tid = threadIdx.x;
    int rg = tid & 31;         // lane -> row sub
    int cg = tid >> 5;         // warp -> col group (8 cols)

    int lrowA = tid >> 1;                 // 0..127
    int lkA   = (tid & 1) * 8;            // 0 or 8
    int rA = blockIdx.x * BM + lrowA;
    int rAc = rA < M ? rA : M - 1;

    int lnB = tid >> 2;                   // 0..63
    int lkB = (tid & 3) * 4;              // 0,4,8,12

    float acc[4][8];
    #pragma unroll
    for (int i = 0; i < 4; i++)
        #pragma unroll
        for (int j = 0; j < 8; j++) acc[i][j] = 0.f;

    // prefetch registers
    float a_ld[8], b_ld[4];

    auto ldg = [&](int k0) {   // k0 = K-offset of tile start; tiles never straddle K1
        const float* Ap; const float* Bp; int lda, ldb, kb;
        if (k0 < K1) { Ap = A1; Bp = B1; lda = lda1; ldb = ldb1; kb = k0; }
        else         { Ap = A2; Bp = B2; lda = lda2; ldb = ldb2; kb = k0 - K1; }
        float4 v0 = *(const float4*)(Ap + (size_t)rAc * lda + kb + lkA);
        float4 v1 = *(const float4*)(Ap + (size_t)rAc * lda + kb + lkA + 4);
        a_ld[0] = v0.x; a_ld[1] = v0.y; a_ld[2] = v0.z; a_ld[3] = v0.w;
        a_ld[4] = v1.x; a_ld[5] = v1.y; a_ld[6] = v1.z; a_ld[7] = v1.w;
        float4 w = *(const float4*)(Bp + (size_t)lnB * ldb + kb + lkB);
        b_ld[0] = w.x; b_ld[1] = w.y; b_ld[2] = w.z; b_ld[3] = w.w;
    };
    auto sts = [&](int buf) {
        #pragma unroll
        for (int j = 0; j < 8; j++) As[buf][lkA + j][lrowA] = a_ld[j];
        #pragma unroll
        for (int j = 0; j < 4; j++) Bs[buf][lkB + j][lnB] = b_ld[j];
    };

    int K = K1 + K2;
    int T = K / BK;            // K1, K2 both multiples of BK
    ldg(0);
    sts(0);
    __syncthreads();

    for (int t = 0; t < T; t++) {
        if (t + 1 < T) ldg((t + 1) * BK);

        int cur = t & 1;
        #pragma unroll
        for (int k = 0; k < BK; k++) {
            float a0 = As[cur][k][rg];
            float a1 = As[cur][k][rg + 32];
            float a2 = As[cur][k][rg + 64];
            float a3 = As[cur][k][rg + 96];
            float4 b0 = *(const float4*)&Bs[cur][k][cg * 8];
            float4 b1 = *(const float4*)&Bs[cur][k][cg * 8 + 4];
            float b[8] = {b0.x, b0.y, b0.z, b0.w, b1.x, b1.y, b1.z, b1.w};
            #pragma unroll
            for (int j = 0; j < 8; j++) {
                acc[0][j] += a0 * b[j];
                acc[1][j] += a1 * b[j];
                acc[2][j] += a2 * b[j];
                acc[3][j] += a3 * b[j];
            }
        }

        if (t + 1 < T) sts((t + 1) & 1);
        __syncthreads();
    }

    float bs[8];
    #pragma unroll
    for (int j = 0; j < 8; j++) bs[j] = bias[cg * 8 + j];

    #pragma unroll
    for (int i = 0; i < 4; i++) {
        int m = blockIdx.x * BM + rg + 32 * i;
        if (m < M) {
            float v[8];
            #pragma unroll
            for (int j = 0; j < 8; j++) {
                float t = acc[i][j] + bs[j];
                v[j] = (mode == 0) ? 0.5f * t : (t > 0.f ? t : 0.01f * t);
            }
            *(float4*)(C + (size_t)m * ldc + cg * 8)     = make_float4(v[0], v[1], v[2], v[3]);
            *(float4*)(C + (size_t)m * ldc + cg * 8 + 4) = make_float4(v[4], v[5], v[6], v[7]);
        }
    }
}

// ---------------- SpMM scatter: nb[row] += val * cur[col] ----------------
// 16 lanes per edge, each lane handles one float4 of the 64-wide row.
__global__ __launch_bounds__(256)
void spmm_scatter(const int* __restrict__ rows, const int* __restrict__ cols,
                  const float* __restrict__ vals,
                  const float* __restrict__ cur, int ld_cur)
{
    long t = (long)blockIdx.x * blockDim.x + threadIdx.x;
    int e = (int)(t >> 4);
    int c = (int)(t & 15);
    if (e >= NNZ) return;
    int r = rows[e];
    int cl = cols[e];
    float v = vals[e];
    float4 x = *(const float4*)(cur + (size_t)cl * ld_cur + c * 4);
    float* dst = g_nb + (size_t)r * EMB + c * 4;
    asm volatile("red.global.add.v4.f32 [%0], {%1, %2, %3, %4};"
                 :: "l"(dst), "f"(x.x * v), "f"(x.y * v), "f"(x.z * v), "f"(x.w * v)
                 : "memory");
}

// ---------------- launch ----------------
extern "C" void kernel_launch(void* const* d_in, const int* in_sizes, int n_in,
                              void* d_out, int out_size)
{
    const int*   adj_row = (const int*)  d_in[0];
    const int*   adj_col = (const int*)  d_in[1];
    const float* adj_val = (const float*)d_in[2];
    const float* embedding = (const float*)d_in[3];
    const float* visual  = (const float*)d_in[4];
    const float* text    = (const float*)d_in[5];
    const float* Wv1 = (const float*)d_in[6];  const float* bv1 = (const float*)d_in[7];
    const float* Wv2 = (const float*)d_in[8];  const float* bv2 = (const float*)d_in[9];
    const float* Wt1 = (const float*)d_in[10]; const float* bt1 = (const float*)d_in[11];
    const float* Wt2 = (const float*)d_in[12]; const float* bt2 = (const float*)d_in[13];
    const float* Wd  = (const float*)d_in[14]; const float* bd  = (const float*)d_in[15];
    const float* Wc0 = (const float*)d_in[16]; const float* bc0 = (const float*)d_in[17];
    const float* Wc1 = (const float*)d_in[18]; const float* bc1 = (const float*)d_in[19];
    float* out = (float*)d_out;

    float *pH1v, *pH1t, *pNb, *pWv2d, *pWt2d, *pBfuse;
    cudaGetSymbolAddress((void**)&pH1v,  g_H1v);
    cudaGetSymbolAddress((void**)&pH1t,  g_H1t);
    cudaGetSymbolAddress((void**)&pNb,   g_nb);
    cudaGetSymbolAddress((void**)&pWv2d, g_Wv2d);
    cudaGetSymbolAddress((void**)&pWt2d, g_Wt2d);
    cudaGetSymbolAddress((void**)&pBfuse,g_bfuse);

    // 1. fold Wd into the second-layer weights/biases
    combine_w<<<(64*512 + 64*256 + 64 + 255) / 256, 256>>>(Wd, bd, Wv2, bv2, Wt2, bt2);

    // 2. ego = embedding (item rows overwritten by fusion below)
    copy_ego<<<(N_NODES * 16 + 255) / 256, 256>>>(embedding, out);

    // 3. H1v = relu(visual @ Wv1^T + bv1)   [10000, 512], K=2048  (tf32 MMA)
    {
        dim3 grid(512 / 128, (N_ITEMS + 127) / 128);
        mma_nt_relu<true><<<grid, 256>>>(visual, Wv1, bv1, pH1v, N_ITEMS, 512, VIS_DIM);
    }
    // 4. H1t = relu(text @ Wt1^T + bt1)     [10000, 256], K=300   (tf32 MMA, tail-guarded)
    {
        dim3 grid(256 / 128, (N_ITEMS + 127) / 128);
        mma_nt_relu<false><<<grid, 256>>>(text, Wt1, bt1, pH1t, N_ITEMS, 256, TXT_DIM);
    }
    // 5. fused_item -> ego item rows: 0.5*(H1v@Wv2d^T + H1t@Wt2d^T + bfuse)
    gemm_n64<<<(N_ITEMS + 127) / 128, 256>>>(
        pH1v, 512, 512, pH1t, 256, 256,
        pWv2d, 512, pWt2d, 256,
        pBfuse, out + (size_t)N_USERS * OUT_COLS, OUT_COLS, N_ITEMS, 0);

    // ---- layer 1 ----
    zero_nb<<<(N_NODES * 16 + 255) / 256, 256>>>();
    spmm_scatter<<<(int)(((long)NNZ * 16 + 255) / 256), 256>>>(
        adj_row, adj_col, adj_val, out /*ego, cols 0:64*/, OUT_COLS);
    gemm_n64<<<(N_NODES + 127) / 128, 256>>>(
        out, OUT_COLS, 64, pNb, EMB, 64,
        Wc0, 128, Wc0 + 64, 128,
        bc0, out + 64, OUT_COLS, N_NODES, 1);

    // ---- layer 2 ----
    zero_nb<<<(N_NODES * 16 + 255) / 256, 256>>>();
    spmm_scatter<<<(int)(((long)NNZ * 16 + 255) / 256), 256>>>(
        adj_row, adj_col, adj_val, out + 64 /*cur1, cols 64:128*/, OUT_COLS);
    gemm_n64<<<(N_NODES + 127) / 128, 256>>>(
        out + 64, OUT_COLS, 64, pNb, EMB, 64,
        Wc1, 128, Wc1 + 64, 128,
        bc1, out + 128, OUT_COLS, N_NODES, 1);
}

// round 9
// speedup vs baseline: 2.0351x; 1.2068x over previous
#include <cuda_runtime.h>
#include <cuda_bf16.h>
#include <cstdint>

// ---------------- problem constants ----------------
#define N_USERS   50000
#define N_ITEMS   10000
#define N_NODES   100000
#define EMB       64
#define NNZ       1600000
#define VIS_DIM   2048
#define TXT_DIM   300
#define OUT_COLS  192   // emb * 3

// ---------------- device scratch (static, allocation-free) ----------------
__device__ float g_H1v[N_ITEMS * 512];    // relu(visual @ Wv1^T + bv1)
__device__ float g_H1t[N_ITEMS * 256];    // relu(text  @ Wt1^T + bt1)
__device__ float g_nb [N_NODES * EMB];    // SpMM accumulator
__device__ float g_Wv2d[64 * 512];        // Wd @ Wv2
__device__ float g_Wt2d[64 * 256];        // Wd @ Wt2
__device__ float g_bfuse[64];             // Wd@(bv2+bt2) + 2*bd

// ---------------- weight combination (tiny) ----------------
__global__ void combine_w(const float* __restrict__ Wd, const float* __restrict__ bd,
                          const float* __restrict__ Wv2, const float* __restrict__ bv2,
                          const float* __restrict__ Wt2, const float* __restrict__ bt2)
{
    int idx = blockIdx.x * blockDim.x + threadIdx.x;
    if (idx < 64 * 512) {
        int d = idx >> 9, k = idx & 511;
        float s = 0.f;
        #pragma unroll 8
        for (int o = 0; o < 64; o++) s += Wd[d * 64 + o] * Wv2[o * 512 + k];
        g_Wv2d[idx] = s;
    } else if (idx < 64 * 512 + 64 * 256) {
        int j = idx - 64 * 512;
        int d = j >> 8, k = j & 255;
        float s = 0.f;
        #pragma unroll 8
        for (int o = 0; o < 64; o++) s += Wd[d * 64 + o] * Wt2[o * 256 + k];
        g_Wt2d[j] = s;
    } else if (idx < 64 * 512 + 64 * 256 + 64) {
        int d = idx - (64 * 512 + 64 * 256);
        float s = 2.f * bd[d];
        #pragma unroll 8
        for (int o = 0; o < 64; o++) s += Wd[d * 64 + o] * (bv2[o] + bt2[o]);
        g_bfuse[d] = s;
    }
}

// ---------------- ego copy: embedding -> out[:, 0:64] ----------------
__global__ void copy_ego(const float* __restrict__ emb, float* __restrict__ out)
{
    int i = blockIdx.x * blockDim.x + threadIdx.x;   // over N_NODES*16 float4s
    if (i >= N_NODES * 16) return;
    int row = i >> 4, c = i & 15;
    *(float4*)(out + (size_t)row * OUT_COLS + c * 4) =
        *(const float4*)(emb + (size_t)row * EMB + c * 4);
}

// ---------------- zero SpMM accumulator ----------------
__global__ void zero_nb()
{
    int i = blockIdx.x * blockDim.x + threadIdx.x;
    if (i < N_NODES * 16) ((float4*)g_nb)[i] = make_float4(0.f, 0.f, 0.f, 0.f);
}

// ---------------- tf32 tensor-core GEMM: C = relu(A @ B^T + bias) --------
// A [M,K] row-major, B [N,K] row-major. BM=BN=128, BK=16, 256 threads,
// 8 warps each computing 64x32 via mma.m16n8k8.tf32. cp.async double buffer.
// N must be a multiple of 128. Non-VEC4 path zero-fills the K tail.
template <bool VEC4>
__global__ __launch_bounds__(256, 2)
void mma_nt_relu(const float* __restrict__ A, const float* __restrict__ B,
                 const float* __restrict__ bias, float* __restrict__ C,
                 int M, int N, int K)
{
    const int BK = 16, LDT = 20;   // +4 pad: ldmatrix rows land on disjoint bank quads
    __shared__ float As[2][128][LDT];
    __shared__ float Bs[2][128][LDT];

    int tid = threadIdx.x;
    int lane = tid & 31, wid = tid >> 5;
    int wm = wid >> 2;     // 0..1 : 64-row half
    int wn = wid & 3;      // 0..3 : 32-col quarter

    // ---- gmem->smem copy mapping (2 threads per row, 8 floats each) ----
    int row  = tid >> 1;          // 0..127
    int koff = (tid & 1) * 8;     // 0 or 8
    int aRow = blockIdx.y * 128 + row;
    int aRowC = aRow < M ? aRow : M - 1;
    int bRow = blockIdx.x * 128 + row;    // always < N (N % 128 == 0)
    const float* Arow = A + (size_t)aRowC * K + koff;
    const float* Brow = B + (size_t)bRow  * K + koff;

    uint32_t uA[2], uB[2];
    uA[0] = (uint32_t)__cvta_generic_to_shared(&As[0][row][koff]);
    uA[1] = (uint32_t)__cvta_generic_to_shared(&As[1][row][koff]);
    uB[0] = (uint32_t)__cvta_generic_to_shared(&Bs[0][row][koff]);
    uB[1] = (uint32_t)__cvta_generic_to_shared(&Bs[1][row][koff]);

    auto issue = [&](int k0, int buf) {
        #pragma unroll
        for (int c = 0; c < 2; c++) {
            int sz;
            if (VEC4) sz = 16;
            else {
                int rem = K - (k0 + koff + c * 4);      // floats still valid
                sz = rem >= 4 ? 16 : (rem > 0 ? rem * 4 : 0);
            }
            asm volatile("cp.async.ca.shared.global [%0], [%1], 16, %2;"
                         :: "r"(uA[buf] + c * 16), "l"(Arow + k0 + c * 4), "r"(sz) : "memory");
            asm volatile("cp.async.ca.shared.global [%0], [%1], 16, %2;"
                         :: "r"(uB[buf] + c * 16), "l"(Brow + k0 + c * 4), "r"(sz) : "memory");
        }
        asm volatile("cp.async.commit_group;" ::: "memory");
    };

    // ---- ldmatrix per-lane base addresses ----
    int l = lane & 7;
    int selA = lane >> 3;
    int arow0 = wm * 64 + (selA & 1) * 8 + l;
    int acol0 = (selA >> 1) * 4;
    uint32_t aBase[2];
    aBase[0] = (uint32_t)__cvta_generic_to_shared(&As[0][arow0][acol0]);
    aBase[1] = (uint32_t)__cvta_generic_to_shared(&As[1][arow0][acol0]);
    int l16 = lane & 15;
    int brow0 = wn * 32 + (l16 & 7);
    int bcol0 = (l16 >> 3) * 4;
    uint32_t bBase[2];
    bBase[0] = (uint32_t)__cvta_generic_to_shared(&Bs[0][brow0][bcol0]);
    bBase[1] = (uint32_t)__cvta_generic_to_shared(&Bs[1][brow0][bcol0]);

    float acc[4][4][4];
    #pragma unroll
    for (int i = 0; i < 4; i++)
        #pragma unroll
        for (int j = 0; j < 4; j++)
            #pragma unroll
            for (int r = 0; r < 4; r++) acc[i][j][r] = 0.f;

    int T = (K + BK - 1) / BK;
    issue(0, 0);
    asm volatile("cp.async.wait_group 0;" ::: "memory");
    __syncthreads();

    for (int t = 0; t < T; t++) {
        if (t + 1 < T) issue((t + 1) * BK, (t + 1) & 1);

        int cur = t & 1;
        #pragma unroll
        for (int ks = 0; ks < 2; ks++) {
            uint32_t af[4][4], bf[4][2];
            #pragma unroll
            for (int i = 0; i < 4; i++) {
                uint32_t addr = aBase[cur] + (uint32_t)((i * 16 * LDT + ks * 8) * 4);
                asm volatile("ldmatrix.sync.aligned.m8n8.x4.shared.b16 {%0,%1,%2,%3}, [%4];"
                    : "=r"(af[i][0]), "=r"(af[i][1]), "=r"(af[i][2]), "=r"(af[i][3])
                    : "r"(addr));
            }
            #pragma unroll
            for (int j = 0; j < 4; j++) {
                uint32_t addr = bBase[cur] + (uint32_t)((j * 8 * LDT + ks * 8) * 4);
                asm volatile("ldmatrix.sync.aligned.m8n8.x2.shared.b16 {%0,%1}, [%2];"
                    : "=r"(bf[j][0]), "=r"(bf[j][1])
                    : "r"(addr));
            }
            #pragma unroll
            for (int i = 0; i < 4; i++)
                #pragma unroll
                for (int r = 0; r < 4; r++)
                    asm("cvt.rna.tf32.f32 %0, %0;" : "+r"(af[i][r]));
            #pragma unroll
            for (int j = 0; j < 4; j++)
                #pragma unroll
                for (int r = 0; r < 2; r++)
                    asm("cvt.rna.tf32.f32 %0, %0;" : "+r"(bf[j][r]));

            #pragma unroll
            for (int i = 0; i < 4; i++)
                #pragma unroll
                for (int j = 0; j < 4; j++)
                    asm volatile(
                        "mma.sync.aligned.m16n8k8.row.col.f32.tf32.tf32.f32 "
                        "{%0,%1,%2,%3}, {%4,%5,%6,%7}, {%8,%9}, {%0,%1,%2,%3};"
                        : "+f"(acc[i][j][0]), "+f"(acc[i][j][1]),
                          "+f"(acc[i][j][2]), "+f"(acc[i][j][3])
                        : "r"(af[i][0]), "r"(af[i][1]), "r"(af[i][2]), "r"(af[i][3]),
                          "r"(bf[j][0]), "r"(bf[j][1]));
        }

        if (t + 1 < T) asm volatile("cp.async.wait_group 0;" ::: "memory");
        __syncthreads();
    }

    int g = lane >> 2, tq = lane & 3;
    #pragma unroll
    for (int i = 0; i < 4; i++) {
        int m0 = blockIdx.y * 128 + wm * 64 + i * 16 + g;
        #pragma unroll
        for (int j = 0; j < 4; j++) {
            int n0 = blockIdx.x * 128 + wn * 32 + j * 8 + 2 * tq;
            float bv0 = bias[n0], bv1 = bias[n0 + 1];
            if (m0 < M) {
                float2 v = make_float2(fmaxf(acc[i][j][0] + bv0, 0.f),
                                       fmaxf(acc[i][j][1] + bv1, 0.f));
                *(float2*)(C + (size_t)m0 * N + n0) = v;
            }
            if (m0 + 8 < M) {
                float2 v = make_float2(fmaxf(acc[i][j][2] + bv0, 0.f),
                                       fmaxf(acc[i][j][3] + bv1, 0.f));
                *(float2*)(C + (size_t)(m0 + 8) * N + n0) = v;
            }
        }
    }
}

// ---------------- tf32 small GEMM, N=64, split-K two-part inputs ---------
// C[m,n] = epi( A1@B1^T + A2@B2^T + bias ), mode 0: *0.5, mode 1: leaky_relu.
// BM=128, BN=64, BK=16, 8 warps x (32x32) via mma.m16n8k8.tf32.
// Requires K1 % 16 == 0, K2 % 16 == 0, 16B-aligned rows.
__global__ __launch_bounds__(256, 3)
void gemm_n64(const float* __restrict__ A1, int lda1, int K1,
              const float* __restrict__ A2, int lda2, int K2,
              const float* __restrict__ B1, int ldb1,
              const float* __restrict__ B2, int ldb2,
              const float* __restrict__ bias,
              float* __restrict__ C, int ldc, int M, int mode)
{
    const int BK = 16, LDT = 20;
    __shared__ float As[2][128][LDT];
    __shared__ float Bs[2][64][LDT];

    int tid = threadIdx.x;
    int lane = tid & 31, wid = tid >> 5;
    int wm = wid >> 1;     // 0..3 : 32-row quarter
    int wn = wid & 1;      // 0..1 : 32-col half

    // A copy: 2 threads/row, 8 floats each
    int arow  = tid >> 1;
    int akoff = (tid & 1) * 8;
    int rA = blockIdx.x * 128 + arow;
    int rAc = rA < M ? rA : M - 1;
    // B copy: 4 threads/row, 4 floats each (64 rows x 16 k)
    int brow  = tid >> 2;
    int bkoff = (tid & 3) * 4;

    uint32_t uA[2], uB[2];
    uA[0] = (uint32_t)__cvta_generic_to_shared(&As[0][arow][akoff]);
    uA[1] = (uint32_t)__cvta_generic_to_shared(&As[1][arow][akoff]);
    uB[0] = (uint32_t)__cvta_generic_to_shared(&Bs[0][brow][bkoff]);
    uB[1] = (uint32_t)__cvta_generic_to_shared(&Bs[1][brow][bkoff]);

    auto issue = [&](int k0, int buf) {   // tiles never straddle the K1 boundary
        const float* Ap; const float* Bp; int lda, ldb, kb;
        if (k0 < K1) { Ap = A1; Bp = B1; lda = lda1; ldb = ldb1; kb = k0; }
        else         { Ap = A2; Bp = B2; lda = lda2; ldb = ldb2; kb = k0 - K1; }
        const float* as = Ap + (size_t)rAc * lda + kb + akoff;
        asm volatile("cp.async.ca.shared.global [%0], [%1], 16;"
                     :: "r"(uA[buf]), "l"(as) : "memory");
        asm volatile("cp.async.ca.shared.global [%0], [%1], 16;"
                     :: "r"(uA[buf] + 16), "l"(as + 4) : "memory");
        const float* bsrc = Bp + (size_t)brow * ldb + kb + bkoff;
        asm volatile("cp.async.ca.shared.global [%0], [%1], 16;"
                     :: "r"(uB[buf]), "l"(bsrc) : "memory");
        asm volatile("cp.async.commit_group;" ::: "memory");
    };

    // ldmatrix per-lane addresses (same fragment mapping as mma_nt_relu)
    int l = lane & 7;
    int selA = lane >> 3;
    int arow0 = wm * 32 + (selA & 1) * 8 + l;
    int acol0 = (selA >> 1) * 4;
    uint32_t aBase[2];
    aBase[0] = (uint32_t)__cvta_generic_to_shared(&As[0][arow0][acol0]);
    aBase[1] = (uint32_t)__cvta_generic_to_shared(&As[1][arow0][acol0]);
    int l16 = lane & 15;
    int brow0 = wn * 32 + (l16 & 7);
    int bcol0 = (l16 >> 3) * 4;
    uint32_t bBase[2];
    bBase[0] = (uint32_t)__cvta_generic_to_shared(&Bs[0][brow0][bcol0]);
    bBase[1] = (uint32_t)__cvta_generic_to_shared(&Bs[1][brow0][bcol0]);

    float acc[2][4][4];
    #pragma unroll
    for (int i = 0; i < 2; i++)
        #pragma unroll
        for (int j = 0; j < 4; j++)
            #pragma unroll
            for (int r = 0; r < 4; r++) acc[i][j][r] = 0.f;

    int T = (K1 + K2) / BK;
    issue(0, 0);
    asm volatile("cp.async.wait_group 0;" ::: "memory");
    __syncthreads();

    for (int t = 0; t < T; t++) {
        if (t + 1 < T) issue((t + 1) * BK, (t + 1) & 1);

        int cur = t & 1;
        #pragma unroll
        for (int ks = 0; ks < 2; ks++) {
            uint32_t af[2][4], bf[4][2];
            #pragma unroll
            for (int i = 0; i < 2; i++) {
                uint32_t addr = aBase[cur] + (uint32_t)((i * 16 * LDT + ks * 8) * 4);
                asm volatile("ldmatrix.sync.aligned.m8n8.x4.shared.b16 {%0,%1,%2,%3}, [%4];"
                    : "=r"(af[i][0]), "=r"(af[i][1]), "=r"(af[i][2]), "=r"(af[i][3])
                    : "r"(addr));
            }
            #pragma unroll
            for (int j = 0; j < 4; j++) {
                uint32_t addr = bBase[cur] + (uint32_t)((j * 8 * LDT + ks * 8) * 4);
                asm volatile("ldmatrix.sync.aligned.m8n8.x2.shared.b16 {%0,%1}, [%2];"
                    : "=r"(bf[j][0]), "=r"(bf[j][1])
                    : "r"(addr));
            }
            #pragma unroll
            for (int i = 0; i < 2; i++)
                #pragma unroll
                for (int r = 0; r < 4; r++)
                    asm("cvt.rna.tf32.f32 %0, %0;" : "+r"(af[i][r]));
            #pragma unroll
            for (int j = 0; j < 4; j++)
                #pragma unroll
                for (int r = 0; r < 2; r++)
                    asm("cvt.rna.tf32.f32 %0, %0;" : "+r"(bf[j][r]));

            #pragma unroll
            for (int i = 0; i < 2; i++)
                #pragma unroll
                for (int j = 0; j < 4; j++)
                    asm volatile(
                        "mma.sync.aligned.m16n8k8.row.col.f32.tf32.tf32.f32 "
                        "{%0,%1,%2,%3}, {%4,%5,%6,%7}, {%8,%9}, {%0,%1,%2,%3};"
                        : "+f"(acc[i][j][0]), "+f"(acc[i][j][1]),
                          "+f"(acc[i][j][2]), "+f"(acc[i][j][3])
                        : "r"(af[i][0]), "r"(af[i][1]), "r"(af[i][2]), "r"(af[i][3]),
                          "r"(bf[j][0]), "r"(bf[j][1]));
        }

        if (t + 1 < T) asm volatile("cp.async.wait_group 0;" ::: "memory");
        __syncthreads();
    }

    int g = lane >> 2, tq = lane & 3;
    #pragma unroll
    for (int i = 0; i < 2; i++) {
        int m0 = blockIdx.x * 128 + wm * 32 + i * 16 + g;
        #pragma unroll
        for (int j = 0; j < 4; j++) {
            int n0 = wn * 32 + j * 8 + 2 * tq;
            float bv0 = bias[n0], bv1 = bias[n0 + 1];
            #pragma unroll
            for (int h = 0; h < 2; h++) {
                int m = m0 + 8 * h;
                if (m < M) {
                    float t0 = acc[i][j][2 * h]     + bv0;
                    float t1 = acc[i][j][2 * h + 1] + bv1;
                    float2 v;
                    if (mode == 0) { v.x = 0.5f * t0; v.y = 0.5f * t1; }
                    else { v.x = t0 > 0.f ? t0 : 0.01f * t0;
                           v.y = t1 > 0.f ? t1 : 0.01f * t1; }
                    *(float2*)(C + (size_t)m * ldc + n0) = v;
                }
            }
        }
    }
}

// ---------------- SpMM scatter: nb[row] += val * cur[col] ----------------
// 16 lanes per edge, each lane handles one float4 of the 64-wide row.
__global__ __launch_bounds__(256)
void spmm_scatter(const int* __restrict__ rows, const int* __restrict__ cols,
                  const float* __restrict__ vals,
                  const float* __restrict__ cur, int ld_cur)
{
    long t = (long)blockIdx.x * blockDim.x + threadIdx.x;
    int e = (int)(t >> 4);
    int c = (int)(t & 15);
    if (e >= NNZ) return;
    int r = rows[e];
    int cl = cols[e];
    float v = vals[e];
    float4 x = *(const float4*)(cur + (size_t)cl * ld_cur + c * 4);
    float* dst = g_nb + (size_t)r * EMB + c * 4;
    asm volatile("red.global.add.v4.f32 [%0], {%1, %2, %3, %4};"
                 :: "l"(dst), "f"(x.x * v), "f"(x.y * v), "f"(x.z * v), "f"(x.w * v)
                 : "memory");
}

// ---------------- launch ----------------
extern "C" void kernel_launch(void* const* d_in, const int* in_sizes, int n_in,
                              void* d_out, int out_size)
{
    const int*   adj_row = (const int*)  d_in[0];
    const int*   adj_col = (const int*)  d_in[1];
    const float* adj_val = (const float*)d_in[2];
    const float* embedding = (const float*)d_in[3];
    const float* visual  = (const float*)d_in[4];
    const float* text    = (const float*)d_in[5];
    const float* Wv1 = (const float*)d_in[6];  const float* bv1 = (const float*)d_in[7];
    const float* Wv2 = (const float*)d_in[8];  const float* bv2 = (const float*)d_in[9];
    const float* Wt1 = (const float*)d_in[10]; const float* bt1 = (const float*)d_in[11];
    const float* Wt2 = (const float*)d_in[12]; const float* bt2 = (const float*)d_in[13];
    const float* Wd  = (const float*)d_in[14]; const float* bd  = (const float*)d_in[15];
    const float* Wc0 = (const float*)d_in[16]; const float* bc0 = (const float*)d_in[17];
    const float* Wc1 = (const float*)d_in[18]; const float* bc1 = (const float*)d_in[19];
    float* out = (float*)d_out;

    float *pH1v, *pH1t, *pNb, *pWv2d, *pWt2d, *pBfuse;
    cudaGetSymbolAddress((void**)&pH1v,  g_H1v);
    cudaGetSymbolAddress((void**)&pH1t,  g_H1t);
    cudaGetSymbolAddress((void**)&pNb,   g_nb);
    cudaGetSymbolAddress((void**)&pWv2d, g_Wv2d);
    cudaGetSymbolAddress((void**)&pWt2d, g_Wt2d);
    cudaGetSymbolAddress((void**)&pBfuse,g_bfuse);

    // 1. fold Wd into the second-layer weights/biases
    combine_w<<<(64*512 + 64*256 + 64 + 255) / 256, 256>>>(Wd, bd, Wv2, bv2, Wt2, bt2);

    // 2. ego = embedding (item rows overwritten by fusion below)
    copy_ego<<<(N_NODES * 16 + 255) / 256, 256>>>(embedding, out);

    // 3. H1v = relu(visual @ Wv1^T + bv1)   [10000, 512], K=2048  (tf32 MMA)
    {
        dim3 grid(512 / 128, (N_ITEMS + 127) / 128);
        mma_nt_relu<true><<<grid, 256>>>(visual, Wv1, bv1, pH1v, N_ITEMS, 512, VIS_DIM);
    }
    // 4. H1t = relu(text @ Wt1^T + bt1)     [10000, 256], K=300   (tf32 MMA, tail-guarded)
    {
        dim3 grid(256 / 128, (N_ITEMS + 127) / 128);
        mma_nt_relu<false><<<grid, 256>>>(text, Wt1, bt1, pH1t, N_ITEMS, 256, TXT_DIM);
    }
    // 5. fused_item -> ego item rows: 0.5*(H1v@Wv2d^T + H1t@Wt2d^T + bfuse)
    gemm_n64<<<(N_ITEMS + 127) / 128, 256>>>(
        pH1v, 512, 512, pH1t, 256, 256,
        pWv2d, 512, pWt2d, 256,
        pBfuse, out + (size_t)N_USERS * OUT_COLS, OUT_COLS, N_ITEMS, 0);

    // ---- layer 1 ----
    zero_nb<<<(N_NODES * 16 + 255) / 256, 256>>>();
    spmm_scatter<<<(int)(((long)NNZ * 16 + 255) / 256), 256>>>(
        adj_row, adj_col, adj_val, out /*ego, cols 0:64*/, OUT_COLS);
    gemm_n64<<<(N_NODES + 127) / 128, 256>>>(
        out, OUT_COLS, 64, pNb, EMB, 64,
        Wc0, 128, Wc0 + 64, 128,
        bc0, out + 64, OUT_COLS, N_NODES, 1);

    // ---- layer 2 ----
    zero_nb<<<(N_NODES * 16 + 255) / 256, 256>>>();
    spmm_scatter<<<(int)(((long)NNZ * 16 + 255) / 256), 256>>>(
        adj_row, adj_col, adj_val, out + 64 /*cur1, cols 64:128*/, OUT_COLS);
    gemm_n64<<<(N_NODES + 127) / 128, 256>>>(
        out + 64, OUT_COLS, 64, pNb, EMB, 64,
        Wc1, 128, Wc1 + 64, 128,
        bc1, out + 128, OUT_COLS, N_NODES, 1);
}